// round 1
// baseline (speedup 1.0000x reference)
#include <cuda_runtime.h>

// ---------------------------------------------------------------------------
// GNNEncoder: 2x (EdgeConv -> BatchNorm) + mean/max pooling
//
// Key algebra: concat[x_i, x_j-x_i] @ Wa = x_i@(Wtop-Wbot) + x_j@Wbot
//   => per-node A[i] = x_i@(Wtop-Wbot)+ba, B[j] = x_j@Wbot
//   => per-edge first layer is just A[dst]+B[src]
// BatchNorm of layer L is folded (per-channel affine) into the node GEMM of
// layer L+1 and into the pooling pass.
// Edges are counting-sorted by dst so the atomicMax epilogue dedups runs.
// ---------------------------------------------------------------------------

#define HC 64
#define NMAX 50000
#define EMAX 1600000
#define NEG_INF_BITS ((int)0xFF800000u)

__device__ int   g_cnt[NMAX];
__device__ int   g_chunk[256];
__device__ int   g_src[EMAX];
__device__ int   g_dst[EMAX];
__device__ float g_A[NMAX * HC];
__device__ float g_B[NMAX * HC];
__device__ int   g_raw1[NMAX * HC];   // float bits, atomicMax as signed int
__device__ int   g_raw2[NMAX * HC];
__device__ float g_part[128 * 2 * HC];
__device__ float g_scale[2 * HC];
__device__ float g_shift[2 * HC];

// ---------------------------- small utilities ------------------------------

__global__ void k_zero_cnt(int n) {
    int i = blockIdx.x * blockDim.x + threadIdx.x;
    if (i < n) g_cnt[i] = 0;
}

__global__ void k_init_raw(int layer, int n) {
    int* raw = layer ? g_raw2 : g_raw1;
    for (int i = blockIdx.x * blockDim.x + threadIdx.x; i < n;
         i += gridDim.x * blockDim.x)
        raw[i] = NEG_INF_BITS;
}

__global__ void k_hist(const int* __restrict__ dst, int E) {
    for (int e = blockIdx.x * blockDim.x + threadIdx.x; e < E;
         e += gridDim.x * blockDim.x)
        atomicAdd(&g_cnt[dst[e]], 1);
}

__global__ void k_scan1(int n) {  // blockDim = 1024
    __shared__ int s[1024];
    int i = blockIdx.x * 1024 + threadIdx.x;
    int v = (i < n) ? g_cnt[i] : 0;
    s[threadIdx.x] = v;
    __syncthreads();
    for (int off = 1; off < 1024; off <<= 1) {
        int t = 0;
        if (threadIdx.x >= off) t = s[threadIdx.x - off];
        __syncthreads();
        s[threadIdx.x] += t;
        __syncthreads();
    }
    if (i < n) g_cnt[i] = s[threadIdx.x] - v;   // exclusive within chunk
    if (threadIdx.x == 1023) g_chunk[blockIdx.x] = s[1023];
}

__global__ void k_scan2(int nch) {
    if (threadIdx.x == 0 && blockIdx.x == 0) {
        int acc = 0;
        for (int i = 0; i < nch; i++) {
            int t = g_chunk[i];
            g_chunk[i] = acc;
            acc += t;
        }
    }
}

__global__ void k_scan3(int n) {
    int i = blockIdx.x * blockDim.x + threadIdx.x;
    if (i < n) g_cnt[i] += g_chunk[i >> 10];
}

__global__ void k_scatter(const int* __restrict__ src,
                          const int* __restrict__ dst, int E) {
    for (int e = blockIdx.x * blockDim.x + threadIdx.x; e < E;
         e += gridDim.x * blockDim.x) {
        int d = dst[e];
        int p = atomicAdd(&g_cnt[d], 1);
        g_src[p] = src[e];
        g_dst[p] = d;
    }
}

// ------------------------- per-node linear (A, B) ---------------------------
// A = in @ (Wtop - Wbot) + ba ;  B = in @ Wbot
// If use_raw: in[row][k] = bits_as_float(g_raw1[row][k]) * g_scale[k] + g_shift[k]

__global__ __launch_bounds__(256) void k_nodelin(
    const float* __restrict__ xin, int use_raw,
    const float* __restrict__ Wa,  // [128,64] row-major
    const float* __restrict__ ba, int n) {
    __shared__ float Ws[128 * 64];   // 32 KB
    __shared__ float xs[32 * 65];    // padded rows
    int tid = threadIdx.x;
    for (int i = tid; i < 128 * 64; i += 256) Ws[i] = Wa[i];

    int row0 = blockIdx.x * 32;
    for (int i = tid; i < 32 * 64; i += 256) {
        int r = i >> 6, k = i & 63;
        int row = row0 + r;
        float v = 0.f;
        if (row < n) {
            if (use_raw)
                v = __int_as_float(g_raw1[row * 64 + k]) * g_scale[k] + g_shift[k];
            else
                v = xin[row * 64 + k];
        }
        xs[r * 65 + k] = v;
    }
    __syncthreads();

    int r = tid & 31, cg = tid >> 5;
    int c0 = cg * 8;
    float a[8], b[8];
#pragma unroll
    for (int j = 0; j < 8; j++) { a[j] = 0.f; b[j] = 0.f; }

#pragma unroll 8
    for (int k = 0; k < 64; k++) {
        float xv = xs[r * 65 + k];
        const float4* wt = (const float4*)&Ws[k * 64 + c0];
        const float4* wb = (const float4*)&Ws[(64 + k) * 64 + c0];
        float4 t0 = wt[0], t1 = wt[1];
        float4 q0 = wb[0], q1 = wb[1];
        float tw[8] = {t0.x, t0.y, t0.z, t0.w, t1.x, t1.y, t1.z, t1.w};
        float qw[8] = {q0.x, q0.y, q0.z, q0.w, q1.x, q1.y, q1.z, q1.w};
#pragma unroll
        for (int j = 0; j < 8; j++) {
            a[j] = fmaf(xv, tw[j], a[j]);
            b[j] = fmaf(xv, qw[j], b[j]);
        }
    }
    int row = row0 + r;
    if (row < n) {
#pragma unroll
        for (int j = 0; j < 8; j++) {
            float bb = ba[c0 + j];
            g_A[row * 64 + c0 + j] = a[j] - b[j] + bb;
            g_B[row * 64 + c0 + j] = b[j];
        }
    }
}

// ------------------------------ edge kernel --------------------------------
// Per 128-edge tile: t = relu(A[dst]+B[src]) (SMEM, k-split in halves of 32),
// C = t @ Wb (register-tiled GEMM), u = relu(C + bb), segment-dedup atomicMax.

__global__ __launch_bounds__(256) void k_edge(
    const float* __restrict__ Wb,   // [64,64]
    const float* __restrict__ bb,   // [64]
    int E, int layer) {
    __shared__ float Ws[64 * 64];    // 16 KB
    __shared__ float ts[32 * 128];   // 16 KB (k-half x edges)
    __shared__ int ds[128];
    __shared__ int ss[128];

    int* out = layer ? g_raw2 : g_raw1;
    int tid = threadIdx.x;
    int base = blockIdx.x * 128;

    for (int i = tid; i < 4096; i += 256) Ws[i] = Wb[i];
    if (tid < 128) {
        int e = base + tid;
        ds[tid] = (e < E) ? g_dst[e] : -1;
        ss[tid] = (e < E) ? g_src[e] : 0;
    }
    int cg = tid >> 5, eg = tid & 31;
    float bias[8];
#pragma unroll
    for (int j = 0; j < 8; j++) bias[j] = bb[cg * 8 + j];

    float acc[4][8];
#pragma unroll
    for (int i = 0; i < 4; i++)
#pragma unroll
        for (int j = 0; j < 8; j++) acc[i][j] = 0.f;

    __syncthreads();

    for (int half = 0; half < 2; half++) {
        // gather: 2 threads per edge, each covers 16 consecutive k
        int e = tid >> 1, part = tid & 1;
        int d = ds[e];
        int koff = half * 32 + part * 16;
        if (d >= 0) {
            const float4* ap = (const float4*)&g_A[(size_t)d * 64 + koff];
            const float4* bp = (const float4*)&g_B[(size_t)ss[e] * 64 + koff];
#pragma unroll
            for (int q = 0; q < 4; q++) {
                float4 av = ap[q], bv = bp[q];
                int kk = part * 16 + q * 4;
                ts[(kk + 0) * 128 + e] = fmaxf(av.x + bv.x, 0.f);
                ts[(kk + 1) * 128 + e] = fmaxf(av.y + bv.y, 0.f);
                ts[(kk + 2) * 128 + e] = fmaxf(av.z + bv.z, 0.f);
                ts[(kk + 3) * 128 + e] = fmaxf(av.w + bv.w, 0.f);
            }
        } else {
#pragma unroll
            for (int kk = 0; kk < 16; kk++) ts[(part * 16 + kk) * 128 + e] = 0.f;
        }
        __syncthreads();

#pragma unroll 8
        for (int kk = 0; kk < 32; kk++) {
            float4 tv = *(const float4*)(ts + kk * 128 + eg * 4);
            const float* wrow = Ws + (half * 32 + kk) * 64 + cg * 8;
            float4 w0 = *(const float4*)(wrow);
            float4 w1 = *(const float4*)(wrow + 4);
            float ta[4] = {tv.x, tv.y, tv.z, tv.w};
            float wv[8] = {w0.x, w0.y, w0.z, w0.w, w1.x, w1.y, w1.z, w1.w};
#pragma unroll
            for (int i = 0; i < 4; i++)
#pragma unroll
                for (int j = 0; j < 8; j++)
                    acc[i][j] = fmaf(ta[i], wv[j], acc[i][j]);
        }
        __syncthreads();
    }

    // epilogue: relu + run-dedup atomic max (edges sorted by dst)
    int e0 = eg * 4;
#pragma unroll
    for (int j = 0; j < 8; j++) {
        int c = cg * 8 + j;
        int d = ds[e0];
        float m = fmaxf(acc[0][j] + bias[j], 0.f);
#pragma unroll
        for (int i = 1; i < 4; i++) {
            float u = fmaxf(acc[i][j] + bias[j], 0.f);
            int dn = ds[e0 + i];
            if (dn == d) {
                m = fmaxf(m, u);
            } else {
                if (d >= 0) atomicMax(&out[d * 64 + c], __float_as_int(m));
                d = dn;
                m = u;
            }
        }
        if (d >= 0) atomicMax(&out[d * 64 + c], __float_as_int(m));
    }
}

// ------------------------------ batchnorm ----------------------------------

__global__ void k_bnstats(int layer, int n) {  // grid 128, block 256
    const int* raw = layer ? g_raw2 : g_raw1;
    int tid = threadIdx.x;
    int c = tid & 63, gq = tid >> 6;
    float s = 0.f, s2 = 0.f;
    for (int r = blockIdx.x * 4 + gq; r < n; r += 512) {
        float v = __int_as_float(raw[r * 64 + c]);
        s += v;
        s2 += v * v;
    }
    __shared__ float sh[256], sh2[256];
    sh[tid] = s;
    sh2[tid] = s2;
    __syncthreads();
    if (gq == 0) {
#pragma unroll
        for (int q = 1; q < 4; q++) {
            s += sh[q * 64 + c];
            s2 += sh2[q * 64 + c];
        }
        g_part[blockIdx.x * 128 + c] = s;
        g_part[blockIdx.x * 128 + 64 + c] = s2;
    }
}

__global__ void k_bnfinal(const float* __restrict__ gamma,
                          const float* __restrict__ beta, int n, int layer) {
    int c = threadIdx.x;
    if (c < 64) {
        float s = 0.f, s2 = 0.f;
        for (int b = 0; b < 128; b++) {
            s += g_part[b * 128 + c];
            s2 += g_part[b * 128 + 64 + c];
        }
        float mean = s / (float)n;
        float var = s2 / (float)n - mean * mean;
        float sc = gamma[c] * rsqrtf(var + 1e-5f);
        g_scale[layer * 64 + c] = sc;
        g_shift[layer * 64 + c] = beta[c] - mean * sc;
    }
}

// ---------------------- pooling + BN2 finalize + h write --------------------

__global__ __launch_bounds__(256) void k_pool(
    const int* __restrict__ batch, int n, int G,
    float* __restrict__ outh, float* __restrict__ outg) {
    int g = blockIdx.x;
    // lower_bound(g)
    int lo = 0, hi = n;
    while (lo < hi) {
        int mid = (lo + hi) >> 1;
        if (batch[mid] < g) lo = mid + 1; else hi = mid;
    }
    int start = lo;
    hi = n;
    while (lo < hi) {
        int mid = (lo + hi) >> 1;
        if (batch[mid] < g + 1) lo = mid + 1; else hi = mid;
    }
    int end = lo;

    int tid = threadIdx.x;
    int c = tid & 63, gq = tid >> 6;
    float sc = g_scale[64 + c], sh = g_shift[64 + c];
    float s = 0.f, m = __int_as_float(NEG_INF_BITS);
    for (int r = start + gq; r < end; r += 4) {
        float v = __int_as_float(g_raw2[r * 64 + c]) * sc + sh;
        outh[(size_t)r * 64 + c] = v;
        s += v;
        m = fmaxf(m, v);
    }
    __shared__ float shs[256], shm[256];
    shs[tid] = s;
    shm[tid] = m;
    __syncthreads();
    if (gq == 0) {
#pragma unroll
        for (int q = 1; q < 4; q++) {
            s += shs[q * 64 + c];
            m = fmaxf(m, shm[q * 64 + c]);
        }
        int cnt = end - start;
        float mean = s / fmaxf((float)cnt, 1.f);
        float mx = (cnt > 0) ? m : __int_as_float(NEG_INF_BITS);
        outg[g * 128 + c] = mean;
        outg[g * 128 + 64 + c] = mx;
    }
}

// ------------------------------- launch ------------------------------------

extern "C" void kernel_launch(void* const* d_in, const int* in_sizes, int n_in,
                              void* d_out, int out_size) {
    const float* x    = (const float*)d_in[0];
    const int*   ei   = (const int*)d_in[1];
    const int*   batch = (const int*)d_in[2];
    const float* W1a = (const float*)d_in[3];
    const float* b1a = (const float*)d_in[4];
    const float* W1b = (const float*)d_in[5];
    const float* b1b = (const float*)d_in[6];
    const float* g1  = (const float*)d_in[7];
    const float* be1 = (const float*)d_in[8];
    const float* W2a = (const float*)d_in[9];
    const float* b2a = (const float*)d_in[10];
    const float* W2b = (const float*)d_in[11];
    const float* b2b = (const float*)d_in[12];
    const float* g2  = (const float*)d_in[13];
    const float* be2 = (const float*)d_in[14];

    int N = in_sizes[0] / 64;
    int E = in_sizes[1] / 2;
    int G = (out_size - N * 64) / 128;
    const int* src = ei;
    const int* dst = ei + E;

    float* outh = (float*)d_out;
    float* outg = outh + (size_t)N * 64;

    // --- counting sort of edges by dst ---
    k_zero_cnt<<<(N + 255) / 256, 256>>>(N);
    k_hist<<<1024, 256>>>(dst, E);
    int nch = (N + 1023) / 1024;
    k_scan1<<<nch, 1024>>>(N);
    k_scan2<<<1, 32>>>(nch);
    k_scan3<<<(N + 255) / 256, 256>>>(N);
    k_scatter<<<1024, 256>>>(src, dst, E);

    int eblocks = (E + 127) / 128;

    // --- layer 1 ---
    k_nodelin<<<(N + 31) / 32, 256>>>(x, 0, W1a, b1a, N);
    k_init_raw<<<2048, 256>>>(0, N * 64);
    k_edge<<<eblocks, 256>>>(W1b, b1b, E, 0);
    k_bnstats<<<128, 256>>>(0, N);
    k_bnfinal<<<1, 64>>>(g1, be1, N, 0);

    // --- layer 2 (BN1 folded into the node linear via g_scale/g_shift) ---
    k_nodelin<<<(N + 31) / 32, 256>>>(nullptr, 1, W2a, b2a, N);
    k_init_raw<<<2048, 256>>>(1, N * 64);
    k_edge<<<eblocks, 256>>>(W2b, b2b, E, 1);
    k_bnstats<<<128, 256>>>(1, N);
    k_bnfinal<<<1, 64>>>(g2, be2, N, 1);

    // --- BN2 finalize + h write + mean/max pooling ---
    k_pool<<<G, 256>>>(batch, N, G, outh, outg);
}

// round 2
// speedup vs baseline: 1.0570x; 1.0570x over previous
#include <cuda_runtime.h>

// ---------------------------------------------------------------------------
// GNNEncoder: 2x (EdgeConv -> BatchNorm) + mean/max pooling
//
// Key algebra: concat[x_i, x_j-x_i] @ Wa = x_i@(Wtop-Wbot) + x_j@Wbot
//   => per-node A[i] = x_i@(Wtop-Wbot)+ba, B[j] = x_j@Wbot
//   => per-edge first layer is just A[dst]+B[src]
// BatchNorm of layer L is folded into the node GEMM of layer L+1 / pooling.
// Edges counting-sorted by dst => run-dedup of the atomicMax epilogue.
// R2: all hot GEMM loops use packed fma.rn.f32x2 (FFMA2) — 2 fp32 FMAs per
//     fma-pipe issue slot, bit-identical to scalar FFMA.
// ---------------------------------------------------------------------------

#define HC 64
#define NMAX 50000
#define EMAX 1600000
#define NEG_INF_BITS ((int)0xFF800000u)

typedef unsigned long long u64;

#define FMA2(d, a, b, c) \
    asm("fma.rn.f32x2 %0, %1, %2, %3;" : "=l"(d) : "l"(a), "l"(b), "l"(c))
#define PACK2(d, v) \
    asm("mov.b64 %0, {%1, %1};" : "=l"(d) : "r"(v))
#define UNPACK2(lo, hi, v) \
    asm("mov.b64 {%0, %1}, %2;" : "=r"(lo), "=r"(hi) : "l"(v))

__device__ int   g_cnt[NMAX];
__device__ int   g_chunk[256];
__device__ int   g_src[EMAX];
__device__ int   g_dst[EMAX];
__device__ float g_A[NMAX * HC];
__device__ float g_B[NMAX * HC];
__device__ int   g_raw1[NMAX * HC];   // float bits, atomicMax as signed int
__device__ int   g_raw2[NMAX * HC];
__device__ float g_part[128 * 2 * HC];
__device__ float g_scale[2 * HC];
__device__ float g_shift[2 * HC];

// ---------------------------- small utilities ------------------------------

__global__ void k_zero_cnt(int n) {
    int i = blockIdx.x * blockDim.x + threadIdx.x;
    if (i < n) g_cnt[i] = 0;
}

__global__ void k_init_raw(int layer, int n) {
    int* raw = layer ? g_raw2 : g_raw1;
    for (int i = blockIdx.x * blockDim.x + threadIdx.x; i < n;
         i += gridDim.x * blockDim.x)
        raw[i] = NEG_INF_BITS;
}

__global__ void k_hist(const int* __restrict__ dst, int E) {
    for (int e = blockIdx.x * blockDim.x + threadIdx.x; e < E;
         e += gridDim.x * blockDim.x)
        atomicAdd(&g_cnt[dst[e]], 1);
}

__global__ void k_scan1(int n) {  // blockDim = 1024
    __shared__ int s[1024];
    int i = blockIdx.x * 1024 + threadIdx.x;
    int v = (i < n) ? g_cnt[i] : 0;
    s[threadIdx.x] = v;
    __syncthreads();
    for (int off = 1; off < 1024; off <<= 1) {
        int t = 0;
        if (threadIdx.x >= off) t = s[threadIdx.x - off];
        __syncthreads();
        s[threadIdx.x] += t;
        __syncthreads();
    }
    if (i < n) g_cnt[i] = s[threadIdx.x] - v;   // exclusive within chunk
    if (threadIdx.x == 1023) g_chunk[blockIdx.x] = s[1023];
}

__global__ void k_scan2(int nch) {
    if (threadIdx.x == 0 && blockIdx.x == 0) {
        int acc = 0;
        for (int i = 0; i < nch; i++) {
            int t = g_chunk[i];
            g_chunk[i] = acc;
            acc += t;
        }
    }
}

__global__ void k_scan3(int n) {
    int i = blockIdx.x * blockDim.x + threadIdx.x;
    if (i < n) g_cnt[i] += g_chunk[i >> 10];
}

__global__ void k_scatter(const int* __restrict__ src,
                          const int* __restrict__ dst, int E) {
    for (int e = blockIdx.x * blockDim.x + threadIdx.x; e < E;
         e += gridDim.x * blockDim.x) {
        int d = dst[e];
        int p = atomicAdd(&g_cnt[d], 1);
        g_src[p] = src[e];
        g_dst[p] = d;
    }
}

// ------------------------- per-node linear (A, B) ---------------------------
// A = in @ (Wtop - Wbot) + ba ;  B = in @ Wbot   (packed f32x2 inner loop)

__global__ __launch_bounds__(256) void k_nodelin(
    const float* __restrict__ xin, int use_raw,
    const float* __restrict__ Wa,  // [128,64] row-major
    const float* __restrict__ ba, int n) {
    __shared__ float Ws[128 * 64];   // 32 KB
    __shared__ float xs[32 * 65];    // padded rows
    int tid = threadIdx.x;
    for (int i = tid; i < 128 * 64; i += 256) Ws[i] = Wa[i];

    int row0 = blockIdx.x * 32;
    for (int i = tid; i < 32 * 64; i += 256) {
        int r = i >> 6, k = i & 63;
        int row = row0 + r;
        float v = 0.f;
        if (row < n) {
            if (use_raw)
                v = __int_as_float(g_raw1[row * 64 + k]) * g_scale[k] + g_shift[k];
            else
                v = xin[row * 64 + k];
        }
        xs[r * 65 + k] = v;
    }
    __syncthreads();

    int r = tid & 31, cg = tid >> 5;
    int c0 = cg * 8;
    u64 a2[4], b2[4];
#pragma unroll
    for (int j = 0; j < 4; j++) { a2[j] = 0ull; b2[j] = 0ull; }

#pragma unroll 8
    for (int k = 0; k < 64; k++) {
        float xv = xs[r * 65 + k];
        u64 xp;
        PACK2(xp, __float_as_uint(xv));
        ulonglong2 t0 = *(const ulonglong2*)&Ws[k * 64 + c0];
        ulonglong2 t1 = *(const ulonglong2*)&Ws[k * 64 + c0 + 4];
        ulonglong2 q0 = *(const ulonglong2*)&Ws[(64 + k) * 64 + c0];
        ulonglong2 q1 = *(const ulonglong2*)&Ws[(64 + k) * 64 + c0 + 4];
        FMA2(a2[0], xp, t0.x, a2[0]);
        FMA2(a2[1], xp, t0.y, a2[1]);
        FMA2(a2[2], xp, t1.x, a2[2]);
        FMA2(a2[3], xp, t1.y, a2[3]);
        FMA2(b2[0], xp, q0.x, b2[0]);
        FMA2(b2[1], xp, q0.y, b2[1]);
        FMA2(b2[2], xp, q1.x, b2[2]);
        FMA2(b2[3], xp, q1.y, b2[3]);
    }
    int row = row0 + r;
    if (row < n) {
        float a[8], b[8];
#pragma unroll
        for (int j = 0; j < 4; j++) {
            unsigned int lo, hi;
            UNPACK2(lo, hi, a2[j]);
            a[2 * j] = __uint_as_float(lo);
            a[2 * j + 1] = __uint_as_float(hi);
            UNPACK2(lo, hi, b2[j]);
            b[2 * j] = __uint_as_float(lo);
            b[2 * j + 1] = __uint_as_float(hi);
        }
#pragma unroll
        for (int j = 0; j < 8; j++) {
            float bb = ba[c0 + j];
            g_A[row * 64 + c0 + j] = a[j] - b[j] + bb;
            g_B[row * 64 + c0 + j] = b[j];
        }
    }
}

// ------------------------------ edge kernel --------------------------------
// Per 128-edge tile: t = relu(A[dst]+B[src]) (SMEM, k-split in halves of 32),
// C = t @ Wb via packed f32x2 register GEMM, u = relu(C + bb),
// segment-dedup atomicMax.

__global__ __launch_bounds__(256) void k_edge(
    const float* __restrict__ Wb,   // [64,64]
    const float* __restrict__ bb,   // [64]
    int E, int layer) {
    __shared__ float Ws[64 * 64];    // 16 KB
    __shared__ float ts[32 * 128];   // 16 KB (k-half x edges)
    __shared__ int ds[128];
    __shared__ int ss[128];

    int* out = layer ? g_raw2 : g_raw1;
    int tid = threadIdx.x;
    int base = blockIdx.x * 128;

    for (int i = tid; i < 4096; i += 256) Ws[i] = Wb[i];
    if (tid < 128) {
        int e = base + tid;
        ds[tid] = (e < E) ? g_dst[e] : -1;
        ss[tid] = (e < E) ? g_src[e] : 0;
    }
    int cg = tid >> 5, eg = tid & 31;
    float bias[8];
#pragma unroll
    for (int j = 0; j < 8; j++) bias[j] = bb[cg * 8 + j];

    // acc2[edge i][col-pair jp]: packed (col c0+2jp, c0+2jp+1)
    u64 acc2[4][4];
#pragma unroll
    for (int i = 0; i < 4; i++)
#pragma unroll
        for (int j = 0; j < 4; j++) acc2[i][j] = 0ull;

    __syncthreads();

    for (int half = 0; half < 2; half++) {
        // gather: 2 threads per edge, each covers 16 consecutive k
        int e = tid >> 1, part = tid & 1;
        int d = ds[e];
        int koff = half * 32 + part * 16;
        if (d >= 0) {
            const float4* ap = (const float4*)&g_A[(size_t)d * 64 + koff];
            const float4* bp = (const float4*)&g_B[(size_t)ss[e] * 64 + koff];
#pragma unroll
            for (int q = 0; q < 4; q++) {
                float4 av = ap[q], bv = bp[q];
                int kk = part * 16 + q * 4;
                ts[(kk + 0) * 128 + e] = fmaxf(av.x + bv.x, 0.f);
                ts[(kk + 1) * 128 + e] = fmaxf(av.y + bv.y, 0.f);
                ts[(kk + 2) * 128 + e] = fmaxf(av.z + bv.z, 0.f);
                ts[(kk + 3) * 128 + e] = fmaxf(av.w + bv.w, 0.f);
            }
        } else {
#pragma unroll
            for (int kk = 0; kk < 16; kk++) ts[(part * 16 + kk) * 128 + e] = 0.f;
        }
        __syncthreads();

#pragma unroll
        for (int kk = 0; kk < 32; kk++) {
            float4 tv = *(const float4*)(ts + kk * 128 + eg * 4);
            const float* wrow = Ws + (half * 32 + kk) * 64 + cg * 8;
            ulonglong2 wA = *(const ulonglong2*)(wrow);      // cols 0..3
            ulonglong2 wB = *(const ulonglong2*)(wrow + 4);  // cols 4..7
            u64 ta0, ta1, ta2, ta3;
            PACK2(ta0, __float_as_uint(tv.x));
            PACK2(ta1, __float_as_uint(tv.y));
            PACK2(ta2, __float_as_uint(tv.z));
            PACK2(ta3, __float_as_uint(tv.w));
            FMA2(acc2[0][0], ta0, wA.x, acc2[0][0]);
            FMA2(acc2[0][1], ta0, wA.y, acc2[0][1]);
            FMA2(acc2[0][2], ta0, wB.x, acc2[0][2]);
            FMA2(acc2[0][3], ta0, wB.y, acc2[0][3]);
            FMA2(acc2[1][0], ta1, wA.x, acc2[1][0]);
            FMA2(acc2[1][1], ta1, wA.y, acc2[1][1]);
            FMA2(acc2[1][2], ta1, wB.x, acc2[1][2]);
            FMA2(acc2[1][3], ta1, wB.y, acc2[1][3]);
            FMA2(acc2[2][0], ta2, wA.x, acc2[2][0]);
            FMA2(acc2[2][1], ta2, wA.y, acc2[2][1]);
            FMA2(acc2[2][2], ta2, wB.x, acc2[2][2]);
            FMA2(acc2[2][3], ta2, wB.y, acc2[2][3]);
            FMA2(acc2[3][0], ta3, wA.x, acc2[3][0]);
            FMA2(acc2[3][1], ta3, wA.y, acc2[3][1]);
            FMA2(acc2[3][2], ta3, wB.x, acc2[3][2]);
            FMA2(acc2[3][3], ta3, wB.y, acc2[3][3]);
        }
        __syncthreads();
    }

    // unpack accumulators
    float acc[4][8];
#pragma unroll
    for (int i = 0; i < 4; i++)
#pragma unroll
        for (int jp = 0; jp < 4; jp++) {
            unsigned int lo, hi;
            UNPACK2(lo, hi, acc2[i][jp]);
            acc[i][2 * jp] = __uint_as_float(lo);
            acc[i][2 * jp + 1] = __uint_as_float(hi);
        }

    // epilogue: relu + run-dedup atomic max (edges sorted by dst)
    int e0 = eg * 4;
#pragma unroll
    for (int j = 0; j < 8; j++) {
        int c = cg * 8 + j;
        int d = ds[e0];
        float m = fmaxf(acc[0][j] + bias[j], 0.f);
#pragma unroll
        for (int i = 1; i < 4; i++) {
            float u = fmaxf(acc[i][j] + bias[j], 0.f);
            int dn = ds[e0 + i];
            if (dn == d) {
                m = fmaxf(m, u);
            } else {
                if (d >= 0) atomicMax(&out[d * 64 + c], __float_as_int(m));
                d = dn;
                m = u;
            }
        }
        if (d >= 0) atomicMax(&out[d * 64 + c], __float_as_int(m));
    }
}

// ------------------------------ batchnorm ----------------------------------

__global__ void k_bnstats(int layer, int n) {  // grid 128, block 256
    const int* raw = layer ? g_raw2 : g_raw1;
    int tid = threadIdx.x;
    int c = tid & 63, gq = tid >> 6;
    float s = 0.f, s2 = 0.f;
    for (int r = blockIdx.x * 4 + gq; r < n; r += 512) {
        float v = __int_as_float(raw[r * 64 + c]);
        s += v;
        s2 += v * v;
    }
    __shared__ float sh[256], sh2[256];
    sh[tid] = s;
    sh2[tid] = s2;
    __syncthreads();
    if (gq == 0) {
#pragma unroll
        for (int q = 1; q < 4; q++) {
            s += sh[q * 64 + c];
            s2 += sh2[q * 64 + c];
        }
        g_part[blockIdx.x * 128 + c] = s;
        g_part[blockIdx.x * 128 + 64 + c] = s2;
    }
}

__global__ void k_bnfinal(const float* __restrict__ gamma,
                          const float* __restrict__ beta, int n, int layer) {
    int c = threadIdx.x;
    if (c < 64) {
        float s = 0.f, s2 = 0.f;
        for (int b = 0; b < 128; b++) {
            s += g_part[b * 128 + c];
            s2 += g_part[b * 128 + 64 + c];
        }
        float mean = s / (float)n;
        float var = s2 / (float)n - mean * mean;
        float sc = gamma[c] * rsqrtf(var + 1e-5f);
        g_scale[layer * 64 + c] = sc;
        g_shift[layer * 64 + c] = beta[c] - mean * sc;
    }
}

// ---------------------- pooling + BN2 finalize + h write --------------------

__global__ __launch_bounds__(256) void k_pool(
    const int* __restrict__ batch, int n, int G,
    float* __restrict__ outh, float* __restrict__ outg) {
    int g = blockIdx.x;
    int lo = 0, hi = n;
    while (lo < hi) {
        int mid = (lo + hi) >> 1;
        if (batch[mid] < g) lo = mid + 1; else hi = mid;
    }
    int start = lo;
    hi = n;
    while (lo < hi) {
        int mid = (lo + hi) >> 1;
        if (batch[mid] < g + 1) lo = mid + 1; else hi = mid;
    }
    int end = lo;

    int tid = threadIdx.x;
    int c = tid & 63, gq = tid >> 6;
    float sc = g_scale[64 + c], sh = g_shift[64 + c];
    float s = 0.f, m = __int_as_float(NEG_INF_BITS);
    for (int r = start + gq; r < end; r += 4) {
        float v = __int_as_float(g_raw2[r * 64 + c]) * sc + sh;
        outh[(size_t)r * 64 + c] = v;
        s += v;
        m = fmaxf(m, v);
    }
    __shared__ float shs[256], shm[256];
    shs[tid] = s;
    shm[tid] = m;
    __syncthreads();
    if (gq == 0) {
#pragma unroll
        for (int q = 1; q < 4; q++) {
            s += shs[q * 64 + c];
            m = fmaxf(m, shm[q * 64 + c]);
        }
        int cnt = end - start;
        float mean = s / fmaxf((float)cnt, 1.f);
        float mx = (cnt > 0) ? m : __int_as_float(NEG_INF_BITS);
        outg[g * 128 + c] = mean;
        outg[g * 128 + 64 + c] = mx;
    }
}

// ------------------------------- launch ------------------------------------

extern "C" void kernel_launch(void* const* d_in, const int* in_sizes, int n_in,
                              void* d_out, int out_size) {
    const float* x    = (const float*)d_in[0];
    const int*   ei   = (const int*)d_in[1];
    const int*   batch = (const int*)d_in[2];
    const float* W1a = (const float*)d_in[3];
    const float* b1a = (const float*)d_in[4];
    const float* W1b = (const float*)d_in[5];
    const float* b1b = (const float*)d_in[6];
    const float* g1  = (const float*)d_in[7];
    const float* be1 = (const float*)d_in[8];
    const float* W2a = (const float*)d_in[9];
    const float* b2a = (const float*)d_in[10];
    const float* W2b = (const float*)d_in[11];
    const float* b2b = (const float*)d_in[12];
    const float* g2  = (const float*)d_in[13];
    const float* be2 = (const float*)d_in[14];

    int N = in_sizes[0] / 64;
    int E = in_sizes[1] / 2;
    int G = (out_size - N * 64) / 128;
    const int* src = ei;
    const int* dst = ei + E;

    float* outh = (float*)d_out;
    float* outg = outh + (size_t)N * 64;

    // --- counting sort of edges by dst ---
    k_zero_cnt<<<(N + 255) / 256, 256>>>(N);
    k_hist<<<1024, 256>>>(dst, E);
    int nch = (N + 1023) / 1024;
    k_scan1<<<nch, 1024>>>(N);
    k_scan2<<<1, 32>>>(nch);
    k_scan3<<<(N + 255) / 256, 256>>>(N);
    k_scatter<<<1024, 256>>>(src, dst, E);

    int eblocks = (E + 127) / 128;

    // --- layer 1 ---
    k_nodelin<<<(N + 31) / 32, 256>>>(x, 0, W1a, b1a, N);
    k_init_raw<<<2048, 256>>>(0, N * 64);
    k_edge<<<eblocks, 256>>>(W1b, b1b, E, 0);
    k_bnstats<<<128, 256>>>(0, N);
    k_bnfinal<<<1, 64>>>(g1, be1, N, 0);

    // --- layer 2 (BN1 folded into the node linear via g_scale/g_shift) ---
    k_nodelin<<<(N + 31) / 32, 256>>>(nullptr, 1, W2a, b2a, N);
    k_init_raw<<<2048, 256>>>(1, N * 64);
    k_edge<<<eblocks, 256>>>(W2b, b2b, E, 1);
    k_bnstats<<<128, 256>>>(1, N);
    k_bnfinal<<<1, 64>>>(g2, be2, N, 1);

    // --- BN2 finalize + h write + mean/max pooling ---
    k_pool<<<G, 256>>>(batch, N, G, outh, outg);
}

// round 5
// speedup vs baseline: 1.1077x; 1.0480x over previous
#include <cuda_runtime.h>
#include <cuda_fp16.h>
#include <cstdint>

// ---------------------------------------------------------------------------
// GNNEncoder: 2x (EdgeConv -> BatchNorm) + mean/max pooling
//
// Algebra: concat[x_i, x_j-x_i] @ Wa = x_i@(Wtop-Wbot) + x_j@Wbot
//   => per-node A[i], B[j]; per-edge layer-1 is A[dst]+B[src]
// BatchNorm folded into next node GEMM / pooling. Edges counting-sorted by
// dst => run-dedup atomicMax epilogue.
// R4b: edge GEMM on tensor cores via mma.sync.m16n8k16 f16 with 2-way hi/lo
//      split per operand (3 MMA terms, fp32 accumulate) — fp32-grade accuracy.
//      W fragments register-resident; work-stealing tile queue.
// ---------------------------------------------------------------------------

#define HC 64
#define NMAX 50000
#define EMAX 1600000
#define NEG_INF_BITS ((int)0xFF800000u)

typedef unsigned long long u64;

#define FMA2(d, a, b, c) \
    asm("fma.rn.f32x2 %0, %1, %2, %3;" : "=l"(d) : "l"(a), "l"(b), "l"(c))
#define PACK2(d, v) \
    asm("mov.b64 %0, {%1, %1};" : "=l"(d) : "r"(v))
#define UNPACK2(lo, hi, v) \
    asm("mov.b64 {%0, %1}, %2;" : "=r"(lo), "=r"(hi) : "l"(v))

#define MMA16816(c, a0, a1, a2, a3, b0, b1)                                  \
    asm volatile(                                                            \
        "mma.sync.aligned.m16n8k16.row.col.f32.f16.f16.f32 "                 \
        "{%0,%1,%2,%3}, {%4,%5,%6,%7}, {%8,%9}, {%0,%1,%2,%3};"              \
        : "+f"((c)[0]), "+f"((c)[1]), "+f"((c)[2]), "+f"((c)[3])             \
        : "r"(a0), "r"(a1), "r"(a2), "r"(a3), "r"(b0), "r"(b1))

__device__ __forceinline__ uint32_t pack_h2(__half lo, __half hi) {
    return (uint32_t)__half_as_ushort(lo) |
           ((uint32_t)__half_as_ushort(hi) << 16);
}

__device__ int   g_cnt[NMAX];
__device__ int   g_chunk[256];
__device__ int   g_src[EMAX];
__device__ int   g_dst[EMAX];
__device__ float g_A[NMAX * HC];
__device__ float g_B[NMAX * HC];
__device__ int   g_raw1[NMAX * HC];   // float bits, atomicMax as signed int
__device__ int   g_raw2[NMAX * HC];
__device__ float g_part[128 * 2 * HC];
__device__ float g_scale[2 * HC];
__device__ float g_shift[2 * HC];
__device__ unsigned int g_tilectr;    // work-stealing tile counter

// ---------------------------- small utilities ------------------------------

__global__ void k_zero_cnt(int n) {
    int i = blockIdx.x * blockDim.x + threadIdx.x;
    if (i < n) g_cnt[i] = 0;
}

__global__ void k_init_raw(int layer, int n) {
    if (blockIdx.x == 0 && threadIdx.x == 0) g_tilectr = 0;
    int* raw = layer ? g_raw2 : g_raw1;
    for (int i = blockIdx.x * blockDim.x + threadIdx.x; i < n;
         i += gridDim.x * blockDim.x)
        raw[i] = NEG_INF_BITS;
}

__global__ void k_hist(const int* __restrict__ dst, int E) {
    for (int e = blockIdx.x * blockDim.x + threadIdx.x; e < E;
         e += gridDim.x * blockDim.x)
        atomicAdd(&g_cnt[dst[e]], 1);
}

__global__ void k_scan1(int n) {  // blockDim = 1024
    __shared__ int s[1024];
    int i = blockIdx.x * 1024 + threadIdx.x;
    int v = (i < n) ? g_cnt[i] : 0;
    s[threadIdx.x] = v;
    __syncthreads();
    for (int off = 1; off < 1024; off <<= 1) {
        int t = 0;
        if (threadIdx.x >= off) t = s[threadIdx.x - off];
        __syncthreads();
        s[threadIdx.x] += t;
        __syncthreads();
    }
    if (i < n) g_cnt[i] = s[threadIdx.x] - v;   // exclusive within chunk
    if (threadIdx.x == 1023) g_chunk[blockIdx.x] = s[1023];
}

__global__ void k_scan2(int nch) {
    if (threadIdx.x == 0 && blockIdx.x == 0) {
        int acc = 0;
        for (int i = 0; i < nch; i++) {
            int t = g_chunk[i];
            g_chunk[i] = acc;
            acc += t;
        }
    }
}

__global__ void k_scan3(int n) {
    int i = blockIdx.x * blockDim.x + threadIdx.x;
    if (i < n) g_cnt[i] += g_chunk[i >> 10];
}

__global__ void k_scatter(const int* __restrict__ src,
                          const int* __restrict__ dst, int E) {
    for (int e = blockIdx.x * blockDim.x + threadIdx.x; e < E;
         e += gridDim.x * blockDim.x) {
        int d = dst[e];
        int p = atomicAdd(&g_cnt[d], 1);
        g_src[p] = src[e];
        g_dst[p] = d;
    }
}

// ------------------------- per-node linear (A, B) ---------------------------

__global__ __launch_bounds__(256) void k_nodelin(
    const float* __restrict__ xin, int use_raw,
    const float* __restrict__ Wa,  // [128,64] row-major
    const float* __restrict__ ba, int n) {
    __shared__ float Ws[128 * 64];
    __shared__ float xs[32 * 65];
    int tid = threadIdx.x;
    for (int i = tid; i < 128 * 64; i += 256) Ws[i] = Wa[i];

    int row0 = blockIdx.x * 32;
    for (int i = tid; i < 32 * 64; i += 256) {
        int r = i >> 6, k = i & 63;
        int row = row0 + r;
        float v = 0.f;
        if (row < n) {
            if (use_raw)
                v = __int_as_float(g_raw1[row * 64 + k]) * g_scale[k] + g_shift[k];
            else
                v = xin[row * 64 + k];
        }
        xs[r * 65 + k] = v;
    }
    __syncthreads();

    int r = tid & 31, cg = tid >> 5;
    int c0 = cg * 8;
    u64 a2[4], b2[4];
#pragma unroll
    for (int j = 0; j < 4; j++) { a2[j] = 0ull; b2[j] = 0ull; }

#pragma unroll 8
    for (int k = 0; k < 64; k++) {
        float xv = xs[r * 65 + k];
        u64 xp;
        PACK2(xp, __float_as_uint(xv));
        ulonglong2 t0 = *(const ulonglong2*)&Ws[k * 64 + c0];
        ulonglong2 t1 = *(const ulonglong2*)&Ws[k * 64 + c0 + 4];
        ulonglong2 q0 = *(const ulonglong2*)&Ws[(64 + k) * 64 + c0];
        ulonglong2 q1 = *(const ulonglong2*)&Ws[(64 + k) * 64 + c0 + 4];
        FMA2(a2[0], xp, t0.x, a2[0]);
        FMA2(a2[1], xp, t0.y, a2[1]);
        FMA2(a2[2], xp, t1.x, a2[2]);
        FMA2(a2[3], xp, t1.y, a2[3]);
        FMA2(b2[0], xp, q0.x, b2[0]);
        FMA2(b2[1], xp, q0.y, b2[1]);
        FMA2(b2[2], xp, q1.x, b2[2]);
        FMA2(b2[3], xp, q1.y, b2[3]);
    }
    int row = row0 + r;
    if (row < n) {
        float a[8], b[8];
#pragma unroll
        for (int j = 0; j < 4; j++) {
            unsigned int lo, hi;
            UNPACK2(lo, hi, a2[j]);
            a[2 * j] = __uint_as_float(lo);
            a[2 * j + 1] = __uint_as_float(hi);
            UNPACK2(lo, hi, b2[j]);
            b[2 * j] = __uint_as_float(lo);
            b[2 * j + 1] = __uint_as_float(hi);
        }
#pragma unroll
        for (int j = 0; j < 8; j++) {
            float bb = ba[c0 + j];
            g_A[row * 64 + c0 + j] = a[j] - b[j] + bb;
            g_B[row * 64 + c0 + j] = b[j];
        }
    }
}

// ----------------- edge kernel (mma.sync f16 hi/lo split) -------------------
// Per 128-edge tile:
//   gather t = relu(A[dst]+B[src]) -> split to f16 hi/lo -> SMEM tiles
//   C = t_hi@W_hi + t_hi@W_lo + t_lo@W_hi  (fp32 accum, HMMA)
//   relu(C + bb) -> staging SMEM -> run-dedup atomicMax (edges sorted by dst)
// 512 threads = 16 warps: warp (eg, nh) = 16 edges x 32 cols.
// W fragments register-resident for the whole kernel. Tile work-stealing.

#define TILE_E 128
// dynamic smem (bytes)
#define SMO_DS   0
#define SMO_SS   512
#define SMO_AH   1024                      // [128][36] u32 (half2), 18432 B
#define SMO_AL   19456                     // 18432 B
#define SMO_STG  37888                     // [64][132] f32, 33792 B
#define SMO_WTH  37888                     // init-only, [64][33] u32, 8448 B
#define SMO_WTL  46336                     // init-only, 8448 B
#define SM_EDGE_TOTAL 71680

__device__ __forceinline__ void split16(float x, __half& h, __half& l) {
    h = __float2half_rn(x);
    l = __float2half_rn(x - __half2float(h));
}

__global__ __launch_bounds__(512, 1) void k_edge_mma(
    const float* __restrict__ Wb,   // [64k][64n]
    const float* __restrict__ bb,   // [64]
    int E, int layer) {
    extern __shared__ char sm[];
    int* ds = (int*)(sm + SMO_DS);
    int* ss = (int*)(sm + SMO_SS);
    uint32_t* AH = (uint32_t*)(sm + SMO_AH);
    uint32_t* AL = (uint32_t*)(sm + SMO_AL);
    float* STG = (float*)(sm + SMO_STG);
    uint32_t* WTH = (uint32_t*)(sm + SMO_WTH);
    uint32_t* WTL = (uint32_t*)(sm + SMO_WTL);

    int* out = layer ? g_raw2 : g_raw1;
    int tid = threadIdx.x;
    int wid = tid >> 5, lid = tid & 31;
    int gid = lid >> 2, tig = lid & 3;
    int eg = wid & 7, nh = wid >> 3;

    // ---- W split -> SMEM (transposed, half2-packed along k) ----
    for (int i = tid; i < 64 * 32; i += 512) {
        int n = i >> 5, kp = i & 31;
        float w0 = Wb[(2 * kp) * 64 + n];
        float w1 = Wb[(2 * kp + 1) * 64 + n];
        __half h0, l0, h1, l1;
        split16(w0, h0, l0);
        split16(w1, h1, l1);
        WTH[n * 33 + kp] = pack_h2(h0, h1);
        WTL[n * 33 + kp] = pack_h2(l0, l1);
    }
    __syncthreads();

    // ---- W fragments to registers (held for whole kernel) ----
    uint32_t wh0[4][4], wh1[4][4], wl0[4][4], wl1[4][4];
#pragma unroll
    for (int kt = 0; kt < 4; kt++)
#pragma unroll
        for (int nt = 0; nt < 4; nt++) {
            int n = nh * 32 + nt * 8 + gid;
            int kp = kt * 8 + tig;
            wh0[kt][nt] = WTH[n * 33 + kp];
            wh1[kt][nt] = WTH[n * 33 + kp + 4];
            wl0[kt][nt] = WTL[n * 33 + kp];
            wl1[kt][nt] = WTL[n * 33 + kp + 4];
        }
    float bias[4][2];
#pragma unroll
    for (int nt = 0; nt < 4; nt++) {
        int c0 = nh * 32 + nt * 8 + tig * 2;
        bias[nt][0] = bb[c0];
        bias[nt][1] = bb[c0 + 1];
    }
    __syncthreads();   // done with WTH/WTL region (aliases staging)

    int ntiles = (E + TILE_E - 1) / TILE_E;
    __shared__ int s_t;

    for (;;) {
        if (tid == 0) s_t = (int)atomicAdd(&g_tilectr, 1u);
        __syncthreads();              // broadcast tile; fences AH/AL/STG reuse
        int t = s_t;
        if (t >= ntiles) break;
        int base = t * TILE_E;
        if (tid < TILE_E) {
            int e = base + tid;
            ds[tid] = (e < E) ? g_dst[e] : -1;
            ss[tid] = (e < E) ? g_src[e] : 0;
        }
        __syncthreads();

        // ---- gather + relu + f16 split -> SMEM A tiles ----
        {
            int e = tid >> 2, p = tid & 3;       // 4 threads/edge, 16 k each
            int d = ds[e], s = ss[e];
            uint32_t hb[8], lb[8];
            if (d >= 0) {
#pragma unroll
                for (int q = 0; q < 4; q++) {
                    int k = p * 16 + q * 4;
                    float4 av = *(const float4*)&g_A[(size_t)d * 64 + k];
                    float4 bv = *(const float4*)&g_B[(size_t)s * 64 + k];
                    float vx = fmaxf(av.x + bv.x, 0.f);
                    float vy = fmaxf(av.y + bv.y, 0.f);
                    float vz = fmaxf(av.z + bv.z, 0.f);
                    float vw = fmaxf(av.w + bv.w, 0.f);
                    __half hx, lx, hy, ly, hz, lz, hw, lw;
                    split16(vx, hx, lx);
                    split16(vy, hy, ly);
                    split16(vz, hz, lz);
                    split16(vw, hw, lw);
                    hb[2 * q]     = pack_h2(hx, hy);
                    hb[2 * q + 1] = pack_h2(hz, hw);
                    lb[2 * q]     = pack_h2(lx, ly);
                    lb[2 * q + 1] = pack_h2(lz, lw);
                }
            } else {
#pragma unroll
                for (int q = 0; q < 8; q++) { hb[q] = 0u; lb[q] = 0u; }
            }
            uint32_t* ah = AH + e * 36 + p * 8;
            uint32_t* al = AL + e * 36 + p * 8;
#pragma unroll
            for (int q = 0; q < 4; q++) {
                ((uint2*)ah)[q] = make_uint2(hb[2 * q], hb[2 * q + 1]);
                ((uint2*)al)[q] = make_uint2(lb[2 * q], lb[2 * q + 1]);
            }
        }
        __syncthreads();

        // ---- tensor-core GEMM: 4 k-tiles x 4 n-tiles x 3 split terms ----
        float acc[4][4];
#pragma unroll
        for (int nt = 0; nt < 4; nt++)
#pragma unroll
            for (int j = 0; j < 4; j++) acc[nt][j] = 0.f;

        int erow = eg * 16 + gid;
#pragma unroll
        for (int kt = 0; kt < 4; kt++) {
            int kp = kt * 8 + tig;
            uint32_t ah0 = AH[erow * 36 + kp];
            uint32_t ah1 = AH[(erow + 8) * 36 + kp];
            uint32_t ah2 = AH[erow * 36 + kp + 4];
            uint32_t ah3 = AH[(erow + 8) * 36 + kp + 4];
            uint32_t al0 = AL[erow * 36 + kp];
            uint32_t al1 = AL[(erow + 8) * 36 + kp];
            uint32_t al2 = AL[erow * 36 + kp + 4];
            uint32_t al3 = AL[(erow + 8) * 36 + kp + 4];
#pragma unroll
            for (int nt = 0; nt < 4; nt++) {
                MMA16816(acc[nt], ah0, ah1, ah2, ah3, wh0[kt][nt], wh1[kt][nt]);
                MMA16816(acc[nt], ah0, ah1, ah2, ah3, wl0[kt][nt], wl1[kt][nt]);
                MMA16816(acc[nt], al0, al1, al2, al3, wh0[kt][nt], wh1[kt][nt]);
            }
        }

        // ---- bias + relu -> staging (col-major [col][edge], stride 132) ----
#pragma unroll
        for (int nt = 0; nt < 4; nt++) {
            int c0 = nh * 32 + nt * 8 + tig * 2;
            STG[c0 * 132 + erow]           = fmaxf(acc[nt][0] + bias[nt][0], 0.f);
            STG[(c0 + 1) * 132 + erow]     = fmaxf(acc[nt][1] + bias[nt][1], 0.f);
            STG[c0 * 132 + erow + 8]       = fmaxf(acc[nt][2] + bias[nt][0], 0.f);
            STG[(c0 + 1) * 132 + erow + 8] = fmaxf(acc[nt][3] + bias[nt][1], 0.f);
        }
        __syncthreads();

        // ---- run-dedup atomicMax (edges sorted by dst) ----
        {
            int c = tid >> 3;
            int seg = (tid & 7) * 16;
            const float* p = STG + c * 132 + seg;
            float v[16];
#pragma unroll
            for (int q = 0; q < 4; q++) {
                float4 f = *(const float4*)(p + q * 4);
                v[q * 4 + 0] = f.x; v[q * 4 + 1] = f.y;
                v[q * 4 + 2] = f.z; v[q * 4 + 3] = f.w;
            }
            int d = ds[seg];
            float m = v[0];
#pragma unroll
            for (int i = 1; i < 16; i++) {
                int dn = ds[seg + i];
                if (dn == d) {
                    m = fmaxf(m, v[i]);
                } else {
                    if (d >= 0) atomicMax(&out[d * 64 + c], __float_as_int(m));
                    d = dn;
                    m = v[i];
                }
            }
            if (d >= 0) atomicMax(&out[d * 64 + c], __float_as_int(m));
        }
    }
}

// ------------------------------ batchnorm ----------------------------------

__global__ void k_bnstats(int layer, int n) {  // grid 128, block 256
    const int* raw = layer ? g_raw2 : g_raw1;
    int tid = threadIdx.x;
    int c = tid & 63, gq = tid >> 6;
    float s = 0.f, s2 = 0.f;
    for (int r = blockIdx.x * 4 + gq; r < n; r += 512) {
        float v = __int_as_float(raw[r * 64 + c]);
        s += v;
        s2 += v * v;
    }
    __shared__ float sh[256], sh2[256];
    sh[tid] = s;
    sh2[tid] = s2;
    __syncthreads();
    if (gq == 0) {
#pragma unroll
        for (int q = 1; q < 4; q++) {
            s += sh[q * 64 + c];
            s2 += sh2[q * 64 + c];
        }
        g_part[blockIdx.x * 128 + c] = s;
        g_part[blockIdx.x * 128 + 64 + c] = s2;
    }
}

__global__ void k_bnfinal(const float* __restrict__ gamma,
                          const float* __restrict__ beta, int n, int layer) {
    int c = threadIdx.x;
    if (c < 64) {
        float s = 0.f, s2 = 0.f;
        for (int b = 0; b < 128; b++) {
            s += g_part[b * 128 + c];
            s2 += g_part[b * 128 + 64 + c];
        }
        float mean = s / (float)n;
        float var = s2 / (float)n - mean * mean;
        float sc = gamma[c] * rsqrtf(var + 1e-5f);
        g_scale[layer * 64 + c] = sc;
        g_shift[layer * 64 + c] = beta[c] - mean * sc;
    }
}

// ---------------------- pooling + BN2 finalize + h write --------------------

__global__ __launch_bounds__(256) void k_pool(
    const int* __restrict__ batch, int n, int G,
    float* __restrict__ outh, float* __restrict__ outg) {
    int g = blockIdx.x;
    int lo = 0, hi = n;
    while (lo < hi) {
        int mid = (lo + hi) >> 1;
        if (batch[mid] < g) lo = mid + 1; else hi = mid;
    }
    int start = lo;
    hi = n;
    while (lo < hi) {
        int mid = (lo + hi) >> 1;
        if (batch[mid] < g + 1) lo = mid + 1; else hi = mid;
    }
    int end = lo;

    int tid = threadIdx.x;
    int c = tid & 63, gq = tid >> 6;
    float sc = g_scale[64 + c], sh = g_shift[64 + c];
    float s = 0.f, m = __int_as_float(NEG_INF_BITS);
    for (int r = start + gq; r < end; r += 4) {
        float v = __int_as_float(g_raw2[r * 64 + c]) * sc + sh;
        outh[(size_t)r * 64 + c] = v;
        s += v;
        m = fmaxf(m, v);
    }
    __shared__ float shs[256], shm[256];
    shs[tid] = s;
    shm[tid] = m;
    __syncthreads();
    if (gq == 0) {
#pragma unroll
        for (int q = 1; q < 4; q++) {
            s += shs[q * 64 + c];
            m = fmaxf(m, shm[q * 64 + c]);
        }
        int cnt = end - start;
        float mean = s / fmaxf((float)cnt, 1.f);
        float mx = (cnt > 0) ? m : __int_as_float(NEG_INF_BITS);
        outg[g * 128 + c] = mean;
        outg[g * 128 + 64 + c] = mx;
    }
}

// ------------------------------- launch ------------------------------------

extern "C" void kernel_launch(void* const* d_in, const int* in_sizes, int n_in,
                              void* d_out, int out_size) {
    const float* x    = (const float*)d_in[0];
    const int*   ei   = (const int*)d_in[1];
    const int*   batch = (const int*)d_in[2];
    const float* W1a = (const float*)d_in[3];
    const float* b1a = (const float*)d_in[4];
    const float* W1b = (const float*)d_in[5];
    const float* b1b = (const float*)d_in[6];
    const float* g1  = (const float*)d_in[7];
    const float* be1 = (const float*)d_in[8];
    const float* W2a = (const float*)d_in[9];
    const float* b2a = (const float*)d_in[10];
    const float* W2b = (const float*)d_in[11];
    const float* b2b = (const float*)d_in[12];
    const float* g2  = (const float*)d_in[13];
    const float* be2 = (const float*)d_in[14];

    int N = in_sizes[0] / 64;
    int E = in_sizes[1] / 2;
    int G = (out_size - N * 64) / 128;
    const int* src = ei;
    const int* dst = ei + E;

    float* outh = (float*)d_out;
    float* outg = outh + (size_t)N * 64;

    cudaFuncSetAttribute(k_edge_mma,
                         cudaFuncAttributeMaxDynamicSharedMemorySize,
                         SM_EDGE_TOTAL);

    // --- counting sort of edges by dst ---
    k_zero_cnt<<<(N + 255) / 256, 256>>>(N);
    k_hist<<<1024, 256>>>(dst, E);
    int nch = (N + 1023) / 1024;
    k_scan1<<<nch, 1024>>>(N);
    k_scan2<<<1, 32>>>(nch);
    k_scan3<<<(N + 255) / 256, 256>>>(N);
    k_scatter<<<1024, 256>>>(src, dst, E);

    // --- layer 1 ---
    k_nodelin<<<(N + 31) / 32, 256>>>(x, 0, W1a, b1a, N);
    k_init_raw<<<2048, 256>>>(0, N * 64);
    k_edge_mma<<<152, 512, SM_EDGE_TOTAL>>>(W1b, b1b, E, 0);
    k_bnstats<<<128, 256>>>(0, N);
    k_bnfinal<<<1, 64>>>(g1, be1, N, 0);

    // --- layer 2 (BN1 folded into the node linear via g_scale/g_shift) ---
    k_nodelin<<<(N + 31) / 32, 256>>>(nullptr, 1, W2a, b2a, N);
    k_init_raw<<<2048, 256>>>(1, N * 64);
    k_edge_mma<<<152, 512, SM_EDGE_TOTAL>>>(W2b, b2b, E, 1);
    k_bnstats<<<128, 256>>>(1, N);
    k_bnfinal<<<1, 64>>>(g2, be2, N, 1);

    // --- BN2 finalize + h write + mean/max pooling ---
    k_pool<<<G, 256>>>(batch, N, G, outh, outg);
}

// round 6
// speedup vs baseline: 1.1207x; 1.0117x over previous
#include <cuda_runtime.h>
#include <cuda_fp16.h>
#include <cstdint>

// ---------------------------------------------------------------------------
// GNNEncoder: 2x (EdgeConv -> BatchNorm) + mean/max pooling
//
// Algebra: concat[x_i, x_j-x_i] @ Wa = x_i@(Wtop-Wbot) + x_j@Wbot
//   => per-node A[i], B[j]; per-edge layer-1 is A[dst]+B[src]
// BatchNorm folded into next node GEMM / pooling. Edges counting-sorted by
// dst => run-dedup atomicMax epilogue.
// R6: software-pipelined edge kernel (gather of tile t+1 overlaps MMA of t),
//     3-term f16 split with fp32 accum for hi*hi and f16 accum for the two
//     low-order terms (error ~2^-21, free speed if f16-acc HMMA is 2x).
// ---------------------------------------------------------------------------

#define HC 64
#define NMAX 50000
#define EMAX 1600000
#define NEG_INF_BITS ((int)0xFF800000u)

typedef unsigned long long u64;

#define FMA2(d, a, b, c) \
    asm("fma.rn.f32x2 %0, %1, %2, %3;" : "=l"(d) : "l"(a), "l"(b), "l"(c))
#define PACK2(d, v) \
    asm("mov.b64 %0, {%1, %1};" : "=l"(d) : "r"(v))
#define UNPACK2(lo, hi, v) \
    asm("mov.b64 {%0, %1}, %2;" : "=r"(lo), "=r"(hi) : "l"(v))

// fp32-accumulator HMMA
#define MMA16816(c, a0, a1, a2, a3, b0, b1)                                  \
    asm volatile(                                                            \
        "mma.sync.aligned.m16n8k16.row.col.f32.f16.f16.f32 "                 \
        "{%0,%1,%2,%3}, {%4,%5,%6,%7}, {%8,%9}, {%0,%1,%2,%3};"              \
        : "+f"((c)[0]), "+f"((c)[1]), "+f"((c)[2]), "+f"((c)[3])             \
        : "r"(a0), "r"(a1), "r"(a2), "r"(a3), "r"(b0), "r"(b1))

// fp16-accumulator HMMA (low-order terms)
#define MMA16816H(cd, a0, a1, a2, a3, b0, b1)                                \
    asm volatile(                                                            \
        "mma.sync.aligned.m16n8k16.row.col.f16.f16.f16.f16 "                 \
        "{%0,%1}, {%2,%3,%4,%5}, {%6,%7}, {%0,%1};"                          \
        : "+r"((cd)[0]), "+r"((cd)[1])                                       \
        : "r"(a0), "r"(a1), "r"(a2), "r"(a3), "r"(b0), "r"(b1))

__device__ __forceinline__ uint32_t pack_h2(__half lo, __half hi) {
    return (uint32_t)__half_as_ushort(lo) |
           ((uint32_t)__half_as_ushort(hi) << 16);
}

__device__ int   g_cnt[NMAX];
__device__ int   g_chunk[256];
__device__ int   g_src[EMAX];
__device__ int   g_dst[EMAX];
__device__ float g_A[NMAX * HC];
__device__ float g_B[NMAX * HC];
__device__ int   g_raw1[NMAX * HC];   // float bits, atomicMax as signed int
__device__ int   g_raw2[NMAX * HC];
__device__ float g_part[128 * 2 * HC];
__device__ float g_scale[2 * HC];
__device__ float g_shift[2 * HC];

// ---------------------------- small utilities ------------------------------

__global__ void k_zero_cnt(int n) {
    int i = blockIdx.x * blockDim.x + threadIdx.x;
    if (i < n) g_cnt[i] = 0;
}

__global__ void k_init_raw(int layer, int n) {
    int* raw = layer ? g_raw2 : g_raw1;
    for (int i = blockIdx.x * blockDim.x + threadIdx.x; i < n;
         i += gridDim.x * blockDim.x)
        raw[i] = NEG_INF_BITS;
}

__global__ void k_hist(const int* __restrict__ dst, int E) {
    for (int e = blockIdx.x * blockDim.x + threadIdx.x; e < E;
         e += gridDim.x * blockDim.x)
        atomicAdd(&g_cnt[dst[e]], 1);
}

__global__ void k_scan1(int n) {  // blockDim = 1024
    __shared__ int s[1024];
    int i = blockIdx.x * 1024 + threadIdx.x;
    int v = (i < n) ? g_cnt[i] : 0;
    s[threadIdx.x] = v;
    __syncthreads();
    for (int off = 1; off < 1024; off <<= 1) {
        int t = 0;
        if (threadIdx.x >= off) t = s[threadIdx.x - off];
        __syncthreads();
        s[threadIdx.x] += t;
        __syncthreads();
    }
    if (i < n) g_cnt[i] = s[threadIdx.x] - v;   // exclusive within chunk
    if (threadIdx.x == 1023) g_chunk[blockIdx.x] = s[1023];
}

__global__ void k_scan2(int nch) {
    if (threadIdx.x == 0 && blockIdx.x == 0) {
        int acc = 0;
        for (int i = 0; i < nch; i++) {
            int t = g_chunk[i];
            g_chunk[i] = acc;
            acc += t;
        }
    }
}

__global__ void k_scan3(int n) {
    int i = blockIdx.x * blockDim.x + threadIdx.x;
    if (i < n) g_cnt[i] += g_chunk[i >> 10];
}

__global__ void k_scatter(const int* __restrict__ src,
                          const int* __restrict__ dst, int E) {
    for (int e = blockIdx.x * blockDim.x + threadIdx.x; e < E;
         e += gridDim.x * blockDim.x) {
        int d = dst[e];
        int p = atomicAdd(&g_cnt[d], 1);
        g_src[p] = src[e];
        g_dst[p] = d;
    }
}

// ------------------------- per-node linear (A, B) ---------------------------

__global__ __launch_bounds__(256) void k_nodelin(
    const float* __restrict__ xin, int use_raw,
    const float* __restrict__ Wa,  // [128,64] row-major
    const float* __restrict__ ba, int n) {
    __shared__ float Ws[128 * 64];
    __shared__ float xs[32 * 65];
    int tid = threadIdx.x;
    for (int i = tid; i < 128 * 64; i += 256) Ws[i] = Wa[i];

    int row0 = blockIdx.x * 32;
    for (int i = tid; i < 32 * 64; i += 256) {
        int r = i >> 6, k = i & 63;
        int row = row0 + r;
        float v = 0.f;
        if (row < n) {
            if (use_raw)
                v = __int_as_float(g_raw1[row * 64 + k]) * g_scale[k] + g_shift[k];
            else
                v = xin[row * 64 + k];
        }
        xs[r * 65 + k] = v;
    }
    __syncthreads();

    int r = tid & 31, cg = tid >> 5;
    int c0 = cg * 8;
    u64 a2[4], b2[4];
#pragma unroll
    for (int j = 0; j < 4; j++) { a2[j] = 0ull; b2[j] = 0ull; }

#pragma unroll 8
    for (int k = 0; k < 64; k++) {
        float xv = xs[r * 65 + k];
        u64 xp;
        PACK2(xp, __float_as_uint(xv));
        ulonglong2 t0 = *(const ulonglong2*)&Ws[k * 64 + c0];
        ulonglong2 t1 = *(const ulonglong2*)&Ws[k * 64 + c0 + 4];
        ulonglong2 q0 = *(const ulonglong2*)&Ws[(64 + k) * 64 + c0];
        ulonglong2 q1 = *(const ulonglong2*)&Ws[(64 + k) * 64 + c0 + 4];
        FMA2(a2[0], xp, t0.x, a2[0]);
        FMA2(a2[1], xp, t0.y, a2[1]);
        FMA2(a2[2], xp, t1.x, a2[2]);
        FMA2(a2[3], xp, t1.y, a2[3]);
        FMA2(b2[0], xp, q0.x, b2[0]);
        FMA2(b2[1], xp, q0.y, b2[1]);
        FMA2(b2[2], xp, q1.x, b2[2]);
        FMA2(b2[3], xp, q1.y, b2[3]);
    }
    int row = row0 + r;
    if (row < n) {
        float a[8], b[8];
#pragma unroll
        for (int j = 0; j < 4; j++) {
            unsigned int lo, hi;
            UNPACK2(lo, hi, a2[j]);
            a[2 * j] = __uint_as_float(lo);
            a[2 * j + 1] = __uint_as_float(hi);
            UNPACK2(lo, hi, b2[j]);
            b[2 * j] = __uint_as_float(lo);
            b[2 * j + 1] = __uint_as_float(hi);
        }
#pragma unroll
        for (int j = 0; j < 8; j++) {
            float bb = ba[c0 + j];
            g_A[row * 64 + c0 + j] = a[j] - b[j] + bb;
            g_B[row * 64 + c0 + j] = b[j];
        }
    }
}

// -------------- edge kernel (pipelined, mma.sync hi/lo split) ---------------
// Static tile schedule. Per 128-edge tile, software pipelined:
//   convert(t) -> sync -> issue gather LDG(t+1) -> MMA(t)+STG -> sync ->
//   atomics(t) -> sync -> prefetch ds/ss(t+2)
// 512 threads = 16 warps: warp (eg 0..7, nh 0..1) = 16 edges x 32 cols.

#define TILE_E 128
// dynamic smem (bytes)
#define SMO_DS   0                          // int [2][128]
#define SMO_SS   1024                       // int [2][128]
#define SMO_AH   2048                       // [128][36] u32, 18432 B
#define SMO_AL   20480                      // 18432 B
#define SMO_STG  38912                      // [64][132] f32, 33792 B
#define SMO_WTH  38912                      // init-only alias, [64][33] u32
#define SMO_WTL  47360                      // init-only alias
#define SM_EDGE_TOTAL 72704

__device__ __forceinline__ void split16(float x, __half& h, __half& l) {
    h = __float2half_rn(x);
    l = __float2half_rn(x - __half2float(h));
}

__global__ __launch_bounds__(512, 1) void k_edge_mma(
    const float* __restrict__ Wb,   // [64k][64n]
    const float* __restrict__ bb,   // [64]
    int E, int layer) {
    extern __shared__ char sm[];
    int* dsb = (int*)(sm + SMO_DS);
    int* ssb = (int*)(sm + SMO_SS);
    uint32_t* AH = (uint32_t*)(sm + SMO_AH);
    uint32_t* AL = (uint32_t*)(sm + SMO_AL);
    float* STG = (float*)(sm + SMO_STG);
    uint32_t* WTH = (uint32_t*)(sm + SMO_WTH);
    uint32_t* WTL = (uint32_t*)(sm + SMO_WTL);

    int* out = layer ? g_raw2 : g_raw1;
    int tid = threadIdx.x;
    int wid = tid >> 5, lid = tid & 31;
    int gid = lid >> 2, tig = lid & 3;
    int eg = wid & 7, nh = wid >> 3;

    // ---- W split -> SMEM (transposed, half2-packed along k) ----
    for (int i = tid; i < 64 * 32; i += 512) {
        int n = i >> 5, kp = i & 31;
        float w0 = Wb[(2 * kp) * 64 + n];
        float w1 = Wb[(2 * kp + 1) * 64 + n];
        __half h0, l0, h1, l1;
        split16(w0, h0, l0);
        split16(w1, h1, l1);
        WTH[n * 33 + kp] = pack_h2(h0, h1);
        WTL[n * 33 + kp] = pack_h2(l0, l1);
    }
    __syncthreads();

    // ---- W fragments to registers (held for whole kernel) ----
    uint32_t wh0[4][4], wh1[4][4], wl0[4][4], wl1[4][4];
#pragma unroll
    for (int kt = 0; kt < 4; kt++)
#pragma unroll
        for (int nt = 0; nt < 4; nt++) {
            int n = nh * 32 + nt * 8 + gid;
            int kp = kt * 8 + tig;
            wh0[kt][nt] = WTH[n * 33 + kp];
            wh1[kt][nt] = WTH[n * 33 + kp + 4];
            wl0[kt][nt] = WTL[n * 33 + kp];
            wl1[kt][nt] = WTL[n * 33 + kp + 4];
        }
    float bias[4][2];
#pragma unroll
    for (int nt = 0; nt < 4; nt++) {
        int c0 = nh * 32 + nt * 8 + tig * 2;
        bias[nt][0] = bb[c0];
        bias[nt][1] = bb[c0 + 1];
    }
    __syncthreads();   // done with WTH/WTL region (aliases staging)

    int ntiles = (E + TILE_E - 1) / TILE_E;
    int stride = gridDim.x;
    int t = blockIdx.x;
    if (t >= ntiles) return;

    int ge = tid >> 2, gp = tid & 3;   // gather role: 4 threads/edge, 16 k each

    // ---- prologue: ds/ss(t) -> buf0; gather(t); ds/ss(t+stride) -> buf1 ----
    if (tid < TILE_E) {
        int e = t * TILE_E + tid;
        dsb[tid] = (e < E) ? g_dst[e] : -1;
        ssb[tid] = (e < E) ? g_src[e] : 0;
    }
    __syncthreads();

    float4 ra[4], rb[4];
    {
        int d = dsb[ge], s = ssb[ge];
        if (d >= 0) {
            const float4* ap = (const float4*)&g_A[(size_t)d * 64 + gp * 16];
            const float4* bp = (const float4*)&g_B[(size_t)s * 64 + gp * 16];
#pragma unroll
            for (int q = 0; q < 4; q++) { ra[q] = ap[q]; rb[q] = bp[q]; }
        } else {
#pragma unroll
            for (int q = 0; q < 4; q++) {
                ra[q] = make_float4(0.f, 0.f, 0.f, 0.f);
                rb[q] = ra[q];
            }
        }
    }
    if (tid < TILE_E) {
        long long e = (long long)(t + stride) * TILE_E + tid;
        dsb[128 + tid] = (e < E) ? g_dst[e] : -1;
        ssb[128 + tid] = (e < E) ? g_src[e] : 0;
    }

    int p = 0;
    for (; t < ntiles; t += stride) {
        int tn = t + stride;

        // ---- 1. convert regs (tile t) -> AH/AL ----
        {
            uint32_t* ah = AH + ge * 36 + gp * 8;
            uint32_t* al = AL + ge * 36 + gp * 8;
#pragma unroll
            for (int q = 0; q < 4; q++) {
                float vx = fmaxf(ra[q].x + rb[q].x, 0.f);
                float vy = fmaxf(ra[q].y + rb[q].y, 0.f);
                float vz = fmaxf(ra[q].z + rb[q].z, 0.f);
                float vw = fmaxf(ra[q].w + rb[q].w, 0.f);
                __half hx, lx, hy, ly, hz, lz, hw, lw;
                split16(vx, hx, lx);
                split16(vy, hy, ly);
                split16(vz, hz, lz);
                split16(vw, hw, lw);
                ((uint2*)ah)[q] = make_uint2(pack_h2(hx, hy), pack_h2(hz, hw));
                ((uint2*)al)[q] = make_uint2(pack_h2(lx, ly), pack_h2(lz, lw));
            }
        }
        __syncthreads();   // AH/AL ready; ds/ss[p^1] (tile tn) visible

        // ---- 2. issue gather LDG for tile tn (hidden under MMA) ----
        if (tn < ntiles) {
            int d = dsb[(p ^ 1) * 128 + ge], s = ssb[(p ^ 1) * 128 + ge];
            if (d >= 0) {
                const float4* ap = (const float4*)&g_A[(size_t)d * 64 + gp * 16];
                const float4* bp = (const float4*)&g_B[(size_t)s * 64 + gp * 16];
#pragma unroll
                for (int q = 0; q < 4; q++) { ra[q] = ap[q]; rb[q] = bp[q]; }
            } else {
#pragma unroll
                for (int q = 0; q < 4; q++) {
                    ra[q] = make_float4(0.f, 0.f, 0.f, 0.f);
                    rb[q] = ra[q];
                }
            }
        }

        // ---- 3. MMA: hi*hi in fp32 acc; lo terms in f16 acc ----
        float acc[4][4];
        uint32_t accl[4][2];
#pragma unroll
        for (int nt = 0; nt < 4; nt++) {
#pragma unroll
            for (int j = 0; j < 4; j++) acc[nt][j] = 0.f;
            accl[nt][0] = 0u;
            accl[nt][1] = 0u;
        }

        int erow = eg * 16 + gid;
#pragma unroll
        for (int kt = 0; kt < 4; kt++) {
            int kp = kt * 8 + tig;
            uint32_t ah0 = AH[erow * 36 + kp];
            uint32_t ah1 = AH[(erow + 8) * 36 + kp];
            uint32_t ah2 = AH[erow * 36 + kp + 4];
            uint32_t ah3 = AH[(erow + 8) * 36 + kp + 4];
            uint32_t al0 = AL[erow * 36 + kp];
            uint32_t al1 = AL[(erow + 8) * 36 + kp];
            uint32_t al2 = AL[erow * 36 + kp + 4];
            uint32_t al3 = AL[(erow + 8) * 36 + kp + 4];
#pragma unroll
            for (int nt = 0; nt < 4; nt++) {
                MMA16816(acc[nt], ah0, ah1, ah2, ah3, wh0[kt][nt], wh1[kt][nt]);
                MMA16816H(accl[nt], ah0, ah1, ah2, ah3, wl0[kt][nt], wl1[kt][nt]);
                MMA16816H(accl[nt], al0, al1, al2, al3, wh0[kt][nt], wh1[kt][nt]);
            }
        }

        // ---- bias + relu + lo-merge -> staging [col][edge] stride 132 ----
#pragma unroll
        for (int nt = 0; nt < 4; nt++) {
            __half2 q0 = *reinterpret_cast<__half2*>(&accl[nt][0]);
            __half2 q1 = *reinterpret_cast<__half2*>(&accl[nt][1]);
            float l0 = __low2float(q0), l1 = __high2float(q0);
            float l2 = __low2float(q1), l3 = __high2float(q1);
            int c0 = nh * 32 + nt * 8 + tig * 2;
            STG[c0 * 132 + erow] =
                fmaxf(acc[nt][0] + l0 + bias[nt][0], 0.f);
            STG[(c0 + 1) * 132 + erow] =
                fmaxf(acc[nt][1] + l1 + bias[nt][1], 0.f);
            STG[c0 * 132 + erow + 8] =
                fmaxf(acc[nt][2] + l2 + bias[nt][0], 0.f);
            STG[(c0 + 1) * 132 + erow + 8] =
                fmaxf(acc[nt][3] + l3 + bias[nt][1], 0.f);
        }
        __syncthreads();   // STG ready

        // ---- 4. run-dedup atomicMax (edges sorted by dst) ----
        {
            int c = tid >> 3;
            int seg = (tid & 7) * 16;
            const float* sp = STG + c * 132 + seg;
            const int* dsc = dsb + p * 128;
            float v[16];
#pragma unroll
            for (int q = 0; q < 4; q++) {
                float4 f = *(const float4*)(sp + q * 4);
                v[q * 4 + 0] = f.x; v[q * 4 + 1] = f.y;
                v[q * 4 + 2] = f.z; v[q * 4 + 3] = f.w;
            }
            int d = dsc[seg];
            float m = v[0];
#pragma unroll
            for (int i = 1; i < 16; i++) {
                int dn = dsc[seg + i];
                if (dn == d) {
                    m = fmaxf(m, v[i]);
                } else {
                    if (d >= 0) atomicMax(&out[d * 64 + c], __float_as_int(m));
                    d = dn;
                    m = v[i];
                }
            }
            if (d >= 0) atomicMax(&out[d * 64 + c], __float_as_int(m));
        }
        __syncthreads();   // ds/ss[p] free for reuse

        // ---- 5. prefetch ds/ss (tile t + 2*stride) into buf p ----
        if (tid < TILE_E) {
            long long e = (long long)(t + 2 * stride) * TILE_E + tid;
            dsb[p * 128 + tid] = (e < E) ? g_dst[e] : -1;
            ssb[p * 128 + tid] = (e < E) ? g_src[e] : 0;
        }
        p ^= 1;
    }
}

// ------------------------------ batchnorm ----------------------------------

__global__ void k_bnstats(int layer, int n) {  // grid 128, block 256
    const int* raw = layer ? g_raw2 : g_raw1;
    int tid = threadIdx.x;
    int c = tid & 63, gq = tid >> 6;
    float s = 0.f, s2 = 0.f;
    for (int r = blockIdx.x * 4 + gq; r < n; r += 512) {
        float v = __int_as_float(raw[r * 64 + c]);
        s += v;
        s2 += v * v;
    }
    __shared__ float sh[256], sh2[256];
    sh[tid] = s;
    sh2[tid] = s2;
    __syncthreads();
    if (gq == 0) {
#pragma unroll
        for (int q = 1; q < 4; q++) {
            s += sh[q * 64 + c];
            s2 += sh2[q * 64 + c];
        }
        g_part[blockIdx.x * 128 + c] = s;
        g_part[blockIdx.x * 128 + 64 + c] = s2;
    }
}

__global__ void k_bnfinal(const float* __restrict__ gamma,
                          const float* __restrict__ beta, int n, int layer) {
    int c = threadIdx.x;
    if (c < 64) {
        float s = 0.f, s2 = 0.f;
        for (int b = 0; b < 128; b++) {
            s += g_part[b * 128 + c];
            s2 += g_part[b * 128 + 64 + c];
        }
        float mean = s / (float)n;
        float var = s2 / (float)n - mean * mean;
        float sc = gamma[c] * rsqrtf(var + 1e-5f);
        g_scale[layer * 64 + c] = sc;
        g_shift[layer * 64 + c] = beta[c] - mean * sc;
    }
}

// ---------------------- pooling + BN2 finalize + h write --------------------

__global__ __launch_bounds__(256) void k_pool(
    const int* __restrict__ batch, int n, int G,
    float* __restrict__ outh, float* __restrict__ outg) {
    int g = blockIdx.x;
    int lo = 0, hi = n;
    while (lo < hi) {
        int mid = (lo + hi) >> 1;
        if (batch[mid] < g) lo = mid + 1; else hi = mid;
    }
    int start = lo;
    hi = n;
    while (lo < hi) {
        int mid = (lo + hi) >> 1;
        if (batch[mid] < g + 1) lo = mid + 1; else hi = mid;
    }
    int end = lo;

    int tid = threadIdx.x;
    int c = tid & 63, gq = tid >> 6;
    float sc = g_scale[64 + c], sh = g_shift[64 + c];
    float s = 0.f, m = __int_as_float(NEG_INF_BITS);
    for (int r = start + gq; r < end; r += 4) {
        float v = __int_as_float(g_raw2[r * 64 + c]) * sc + sh;
        outh[(size_t)r * 64 + c] = v;
        s += v;
        m = fmaxf(m, v);
    }
    __shared__ float shs[256], shm[256];
    shs[tid] = s;
    shm[tid] = m;
    __syncthreads();
    if (gq == 0) {
#pragma unroll
        for (int q = 1; q < 4; q++) {
            s += shs[q * 64 + c];
            m = fmaxf(m, shm[q * 64 + c]);
        }
        int cnt = end - start;
        float mean = s / fmaxf((float)cnt, 1.f);
        float mx = (cnt > 0) ? m : __int_as_float(NEG_INF_BITS);
        outg[g * 128 + c] = mean;
        outg[g * 128 + 64 + c] = mx;
    }
}

// ------------------------------- launch ------------------------------------

extern "C" void kernel_launch(void* const* d_in, const int* in_sizes, int n_in,
                              void* d_out, int out_size) {
    const float* x    = (const float*)d_in[0];
    const int*   ei   = (const int*)d_in[1];
    const int*   batch = (const int*)d_in[2];
    const float* W1a = (const float*)d_in[3];
    const float* b1a = (const float*)d_in[4];
    const float* W1b = (const float*)d_in[5];
    const float* b1b = (const float*)d_in[6];
    const float* g1  = (const float*)d_in[7];
    const float* be1 = (const float*)d_in[8];
    const float* W2a = (const float*)d_in[9];
    const float* b2a = (const float*)d_in[10];
    const float* W2b = (const float*)d_in[11];
    const float* b2b = (const float*)d_in[12];
    const float* g2  = (const float*)d_in[13];
    const float* be2 = (const float*)d_in[14];

    int N = in_sizes[0] / 64;
    int E = in_sizes[1] / 2;
    int G = (out_size - N * 64) / 128;
    const int* src = ei;
    const int* dst = ei + E;

    float* outh = (float*)d_out;
    float* outg = outh + (size_t)N * 64;

    cudaFuncSetAttribute(k_edge_mma,
                         cudaFuncAttributeMaxDynamicSharedMemorySize,
                         SM_EDGE_TOTAL);

    // --- counting sort of edges by dst ---
    k_zero_cnt<<<(N + 255) / 256, 256>>>(N);
    k_hist<<<1024, 256>>>(dst, E);
    int nch = (N + 1023) / 1024;
    k_scan1<<<nch, 1024>>>(N);
    k_scan2<<<1, 32>>>(nch);
    k_scan3<<<(N + 255) / 256, 256>>>(N);
    k_scatter<<<1024, 256>>>(src, dst, E);

    // --- layer 1 ---
    k_nodelin<<<(N + 31) / 32, 256>>>(x, 0, W1a, b1a, N);
    k_init_raw<<<2048, 256>>>(0, N * 64);
    k_edge_mma<<<152, 512, SM_EDGE_TOTAL>>>(W1b, b1b, E, 0);
    k_bnstats<<<128, 256>>>(0, N);
    k_bnfinal<<<1, 64>>>(g1, be1, N, 0);

    // --- layer 2 (BN1 folded into the node linear via g_scale/g_shift) ---
    k_nodelin<<<(N + 31) / 32, 256>>>(nullptr, 1, W2a, b2a, N);
    k_init_raw<<<2048, 256>>>(1, N * 64);
    k_edge_mma<<<152, 512, SM_EDGE_TOTAL>>>(W2b, b2b, E, 1);
    k_bnstats<<<128, 256>>>(1, N);
    k_bnfinal<<<1, 64>>>(g2, be2, N, 1);

    // --- BN2 finalize + h write + mean/max pooling ---
    k_pool<<<G, 256>>>(batch, N, G, outh, outg);
}